// round 2
// baseline (speedup 1.0000x reference)
#include <cuda_runtime.h>
#include <math.h>

// Problem constants
// B=8, L=128, QUERY=512, FEAT=2048, HID=512, OUT=512, S=T=100
#define NB   8
#define NL   128
#define QD   512
#define FD   2048
#define HD   512
#define OD   512
#define NS   100
#define NT   100
#define NST  200   // S + T
#define BLROWS (NB*NL)   // 1024

// Scratch (device globals; no allocation allowed)
__device__ float g_q[BLROWS * HD];            // 1024 x 512
__device__ float g_stkey[NB * NST * HD];      // per batch: rows 0..99 = s_key, 100..199 = t_key
__device__ float g_scores[BLROWS * NST];      // raw dots: cols 0..99 = qs, 100..199 = qt
__device__ float g_wst[BLROWS * NST];         // [ws, -wt]
__device__ float g_ctx[BLROWS * HD];

// ---------------------------------------------------------------------------
// Generic tiled fp32 GEMM: C = alpha * A@B (+ bias) (+ C if accum)
// A: M x K row-major (optionally split across A/A2 at row Msplit)
// B: K x N row-major. Batched via blockIdx.z with strides.
// remapKeys: scatter output rows into per-batch [s;t] blocks of g_stkey.
// Tile: BM=128, BN=64, BK=8, 256 threads, 8x4 per-thread microtile.
// ---------------------------------------------------------------------------
#define BM 128
#define BN 64
#define BK 8

__global__ __launch_bounds__(256) void sgemm_kernel(
    const float* __restrict__ A, const float* __restrict__ A2,
    const float* __restrict__ B, const float* __restrict__ bias,
    float* __restrict__ C,
    int M, int N, int K, float alpha, int accum, int remapKeys, int Msplit,
    long long sA, long long sB, long long sC)
{
    A += blockIdx.z * sA;
    B += blockIdx.z * sB;
    C += blockIdx.z * sC;

    __shared__ float As[BK][BM];   // A tile transposed
    __shared__ float Bs[BK][BN];

    const int tid = threadIdx.x;
    const int bx = blockIdx.x, by = blockIdx.y;

    const int arow = tid >> 1;           // 0..127
    const int acol = (tid & 1) * 4;      // 0 or 4
    const int brow = tid >> 5;           // 0..7
    const int bcol = (tid & 31) * 2;     // 0..62

    const int tx = tid & 15;             // 16 col-groups * 4 = 64
    const int ty = tid >> 4;             // 16 row-groups * 8 = 128

    float acc[8][4];
#pragma unroll
    for (int i = 0; i < 8; i++)
#pragma unroll
        for (int j = 0; j < 4; j++) acc[i][j] = 0.f;

    const int gArow = by * BM + arow;
    const float* Arow = nullptr;
    if (gArow < M) {
        if (A2 != nullptr && gArow >= Msplit)
            Arow = A2 + (long long)(gArow - Msplit) * K;
        else
            Arow = A + (long long)gArow * K;
    }

    for (int k0 = 0; k0 < K; k0 += BK) {
        float4 av = Arow ? *(const float4*)(Arow + k0 + acol)
                         : make_float4(0.f, 0.f, 0.f, 0.f);
        As[acol + 0][arow] = av.x;
        As[acol + 1][arow] = av.y;
        As[acol + 2][arow] = av.z;
        As[acol + 3][arow] = av.w;

        float2 bv = *(const float2*)(B + (long long)(k0 + brow) * N + bx * BN + bcol);
        Bs[brow][bcol]     = bv.x;
        Bs[brow][bcol + 1] = bv.y;
        __syncthreads();

#pragma unroll
        for (int k = 0; k < BK; k++) {
            float4 a0 = *(const float4*)&As[k][ty * 8];
            float4 a1 = *(const float4*)&As[k][ty * 8 + 4];
            float4 b0 = *(const float4*)&Bs[k][tx * 4];
            float ar[8] = {a0.x, a0.y, a0.z, a0.w, a1.x, a1.y, a1.z, a1.w};
            float br[4] = {b0.x, b0.y, b0.z, b0.w};
#pragma unroll
            for (int i = 0; i < 8; i++)
#pragma unroll
                for (int j = 0; j < 4; j++)
                    acc[i][j] = fmaf(ar[i], br[j], acc[i][j]);
        }
        __syncthreads();
    }

#pragma unroll
    for (int i = 0; i < 8; i++) {
        int gr = by * BM + ty * 8 + i;
        if (gr >= M) continue;
        int orow = gr;
        if (remapKeys) {
            if (gr < NB * NS) orow = (gr / NS) * NST + gr % NS;
            else {
                int r = gr - NB * NS;
                orow = (r / NT) * NST + NS + r % NT;
            }
        }
#pragma unroll
        for (int j = 0; j < 4; j++) {
            int gc = bx * BN + tx * 4 + j;
            float v = alpha * acc[i][j];
            if (bias)  v += bias[gc];
            if (accum) v += C[(long long)orow * N + gc];
            C[(long long)orow * N + gc] = v;
        }
    }
}

// ---------------------------------------------------------------------------
// Scorer: scores[bl, r] = dot(q[bl,:], stkey[b, r, :]) for r in [0,200)
// Block = (l_tile of 16) x batch. 256 threads = 8 warps; warp per key row.
// ---------------------------------------------------------------------------
__global__ __launch_bounds__(256) void scorer_kernel(
    const float* __restrict__ q, const float* __restrict__ stkey,
    float* __restrict__ scores)
{
    __shared__ float qs[16][HD];   // 32 KB

    const int b = blockIdx.y;
    const int lt = blockIdx.x;     // 0..7 (16 rows each)
    const int tid = threadIdx.x;

    const float* qbase = q + ((long long)b * NL + lt * 16) * HD;
    for (int i = tid; i < 16 * HD / 4; i += 256) {
        float4 v = ((const float4*)qbase)[i];
        ((float4*)&qs[0][0])[i] = v;
    }
    __syncthreads();

    const int w = tid >> 5, lane = tid & 31;

    for (int r = w; r < NST; r += 8) {
        const float* krow = stkey + ((long long)b * NST + r) * HD;
        float4 kv[4];
#pragma unroll
        for (int i = 0; i < 4; i++)
            kv[i] = *(const float4*)&krow[lane * 4 + i * 128];

#pragma unroll
        for (int l = 0; l < 16; l++) {
            float p = 0.f;
#pragma unroll
            for (int i = 0; i < 4; i++) {
                float4 qv = *(const float4*)&qs[l][lane * 4 + i * 128];
                p = fmaf(kv[i].x, qv.x, p);
                p = fmaf(kv[i].y, qv.y, p);
                p = fmaf(kv[i].z, qv.z, p);
                p = fmaf(kv[i].w, qv.w, p);
            }
#pragma unroll
            for (int o = 16; o; o >>= 1)
                p += __shfl_xor_sync(0xFFFFFFFFu, p, o);
            if (lane == 0)
                scores[((long long)b * NL + lt * 16 + l) * NST + r] = p;
        }
    }
}

// ---------------------------------------------------------------------------
// Factorized softmax:
//   ws = softmax_s( qs / 32 ),  wt = softmax_t( -qt / 32 )
// Writes wst[row] = [ws(0..99), -wt(0..99)].
// Block per (b,l) row; warp 0 -> s part, warp 1 -> t part.
// ---------------------------------------------------------------------------
__global__ __launch_bounds__(64) void softmax_kernel(
    const float* __restrict__ scores, float* __restrict__ wst)
{
    const int row = blockIdx.x;
    const int tid = threadIdx.x;
    const int lane = tid & 31, w = tid >> 5;
    const float sgn = (w == 0) ? 1.f : -1.f;
    const float invc = 1.f / 32.f;     // 1/sqrt(2*512)

    const float* sc = scores + (long long)row * NST + w * 100;

    float v[4];
    float mx = -INFINITY;
#pragma unroll
    for (int i = 0; i < 4; i++) {
        int idx = lane + 32 * i;
        float x = (idx < 100) ? sgn * sc[idx] * invc : -INFINITY;
        v[i] = x;
        mx = fmaxf(mx, x);
    }
#pragma unroll
    for (int o = 16; o; o >>= 1)
        mx = fmaxf(mx, __shfl_xor_sync(0xFFFFFFFFu, mx, o));

    float e[4];
    float sum = 0.f;
#pragma unroll
    for (int i = 0; i < 4; i++) {
        int idx = lane + 32 * i;
        e[i] = (idx < 100) ? __expf(v[i] - mx) : 0.f;
        sum += e[i];
    }
#pragma unroll
    for (int o = 16; o; o >>= 1)
        sum += __shfl_xor_sync(0xFFFFFFFFu, sum, o);

    const float inv = sgn / sum;   // +1/sum for ws, -1/sum for wt
#pragma unroll
    for (int i = 0; i < 4; i++) {
        int idx = lane + 32 * i;
        if (idx < 100)
            wst[(long long)row * NST + w * 100 + idx] = e[i] * inv;
    }
}

// ---------------------------------------------------------------------------
extern "C" void kernel_launch(void* const* d_in, const int* in_sizes, int n_in,
                              void* d_out, int out_size)
{
    const float* query = (const float*)d_in[0];
    const float* src   = (const float*)d_in[1];
    const float* trg   = (const float*)d_in[2];
    const float* Wq    = (const float*)d_in[3];
    const float* bq    = (const float*)d_in[4];
    const float* Ws    = (const float*)d_in[5];
    const float* bs    = (const float*)d_in[6];
    const float* Wo    = (const float*)d_in[7];
    const float* bo    = (const float*)d_in[8];
    float* out = (float*)d_out;

    float *q, *stkey, *scores, *wst, *ctx;
    cudaGetSymbolAddress((void**)&q,      g_q);
    cudaGetSymbolAddress((void**)&stkey,  g_stkey);
    cudaGetSymbolAddress((void**)&scores, g_scores);
    cudaGetSymbolAddress((void**)&wst,    g_wst);
    cudaGetSymbolAddress((void**)&ctx,    g_ctx);

    const dim3 blk(256);

    // 1) st_key = [src; trg] @ Ws + bs, scattered to per-batch [s;t] layout
    //    M=1600, N=512, K=2048
    sgemm_kernel<<<dim3(HD / BN, (NB * NST + BM - 1) / BM, 1), blk>>>(
        src, trg, Ws, bs, stkey, NB * NST, HD, FD,
        1.f, 0, 1, NB * NS, 0, 0, 0);

    // 2) q = query @ Wq + bq   (M=1024, N=512, K=512)
    sgemm_kernel<<<dim3(HD / BN, BLROWS / BM, 1), blk>>>(
        query, nullptr, Wq, bq, q, BLROWS, HD, QD,
        1.f, 0, 0, 0, 0, 0, 0);

    // 3) raw scores (q . key) for all 200 keys per (b,l)
    scorer_kernel<<<dim3(NL / 16, NB), 256>>>(q, stkey, scores);

    // 4) factorized softmax -> [ws, -wt]
    softmax_kernel<<<BLROWS, 64>>>(scores, wst);

    // 5) ctx = [ws,-wt] @ st_key / sqrt(2)   batched over b
    //    M=128, N=512, K=200
    sgemm_kernel<<<dim3(HD / BN, 1, NB), blk>>>(
        wst, nullptr, stkey, nullptr, ctx, NL, HD, NST,
        0.70710678118654752f, 0, 0, 0,
        (long long)NL * NST, (long long)NST * HD, (long long)NL * HD);

    // 6) out = query @ Wo_top + bo ; out += ctx @ Wo_bot
    sgemm_kernel<<<dim3(OD / BN, BLROWS / BM, 1), blk>>>(
        query, nullptr, Wo, bo, out, BLROWS, OD, QD,
        1.f, 0, 0, 0, 0, 0, 0);
    sgemm_kernel<<<dim3(OD / BN, BLROWS / BM, 1), blk>>>(
        ctx, nullptr, Wo + (long long)QD * OD, nullptr, out, BLROWS, OD, HD,
        1.f, 1, 0, 0, 0, 0, 0);
}

// round 3
// speedup vs baseline: 1.6757x; 1.6757x over previous
#include <cuda_runtime.h>
#include <cuda_bf16.h>
#include <math.h>
#include <stdint.h>

// Problem constants
#define NB   8
#define NL   128
#define QD   512
#define FD   2048
#define HD   512
#define OD   512
#define NS   100
#define NT   100
#define NST  200
#define BLROWS (NB*NL)   // 1024

// K'-expanded sizes (3x for hi/lo split)
#define KP_KEYS (3*FD)   // 6144
#define KP_Q    (3*QD)   // 1536
#define KP_OUT  (3*(QD+HD)) // 3072

// ---------------- device scratch (no allocation allowed) -------------------
__device__ __align__(128) __nv_bfloat16 g_kA [1600 * KP_KEYS];      // src'|trg'
__device__ __align__(128) __nv_bfloat16 g_Ws2[KP_KEYS * HD];
__device__ __align__(128) __nv_bfloat16 g_oA [BLROWS * KP_OUT];     // query'|ctx'
__device__ __align__(128) __nv_bfloat16 g_Wq2[KP_Q * HD];
__device__ __align__(128) __nv_bfloat16 g_Wo2[KP_OUT * OD];
__device__ __align__(128) float g_q[BLROWS * HD];
__device__ __align__(128) float g_stkey[NB * NST * HD];
__device__ __align__(128) float g_scores[BLROWS * NST];
__device__ __align__(128) float g_wst[BLROWS * NST];
__device__ __align__(128) float g_ctx[BLROWS * HD];

// ---------------- PTX helpers ----------------------------------------------
__device__ __forceinline__ uint32_t smem_u32(const void* p) {
    return (uint32_t)__cvta_generic_to_shared(p);
}
__device__ __forceinline__ void cp_async16(uint32_t dst, const void* src, int sz) {
    asm volatile("cp.async.ca.shared.global [%0], [%1], 16, %2;\n"
                 :: "r"(dst), "l"(src), "r"(sz));
}
__device__ __forceinline__ void cp_commit() {
    asm volatile("cp.async.commit_group;\n");
}
__device__ __forceinline__ void ldsm_x4(uint32_t* d, uint32_t a) {
    asm volatile("ldmatrix.sync.aligned.m8n8.x4.shared.b16 {%0,%1,%2,%3}, [%4];"
                 : "=r"(d[0]), "=r"(d[1]), "=r"(d[2]), "=r"(d[3]) : "r"(a));
}
__device__ __forceinline__ void ldsm_x4_t(uint32_t* d, uint32_t a) {
    asm volatile("ldmatrix.sync.aligned.m8n8.x4.trans.shared.b16 {%0,%1,%2,%3}, [%4];"
                 : "=r"(d[0]), "=r"(d[1]), "=r"(d[2]), "=r"(d[3]) : "r"(a));
}
__device__ __forceinline__ void mma16816(float* c, const uint32_t* a, const uint32_t* b) {
    asm volatile(
        "mma.sync.aligned.m16n8k16.row.col.f32.bf16.bf16.f32 "
        "{%0,%1,%2,%3}, {%4,%5,%6,%7}, {%8,%9}, {%0,%1,%2,%3};"
        : "+f"(c[0]), "+f"(c[1]), "+f"(c[2]), "+f"(c[3])
        : "r"(a[0]), "r"(a[1]), "r"(a[2]), "r"(a[3]), "r"(b[0]), "r"(b[1]));
}

// ---------------- fp32 -> bf16 hi/lo expansion ------------------------------
// A-style: in [R][C] fp32 -> out rows [R][3C] pattern (hi, hi, lo), row stride ostride
__global__ void convA_kernel(const float* __restrict__ in, __nv_bfloat16* __restrict__ out,
                             int n, int C, int ostride) {
    for (int i = blockIdx.x * blockDim.x + threadIdx.x; i < n; i += gridDim.x * blockDim.x) {
        int r = i / C, c = i % C;
        float x = in[i];
        __nv_bfloat16 bh = __float2bfloat16_rn(x);
        __nv_bfloat16 bl = __float2bfloat16_rn(x - __bfloat162float(bh));
        __nv_bfloat16* o = out + (size_t)r * ostride + 3 * c;
        o[0] = bh; o[1] = bh; o[2] = bl;
    }
}
// B-style: in [R][C] fp32 -> out [3R][C] pattern rows (hi, lo, hi)
__global__ void convB_kernel(const float* __restrict__ in, __nv_bfloat16* __restrict__ out,
                             int n, int C) {
    for (int i = blockIdx.x * blockDim.x + threadIdx.x; i < n; i += gridDim.x * blockDim.x) {
        int r = i / C, c = i % C;
        float x = in[i];
        __nv_bfloat16 bh = __float2bfloat16_rn(x);
        __nv_bfloat16 bl = __float2bfloat16_rn(x - __bfloat162float(bh));
        __nv_bfloat16* o = out + (size_t)(3 * r) * C + c;
        o[0] = bh; o[C] = bl; o[2 * C] = bh;
    }
}

// ---------------- bf16 tensor-core GEMM -------------------------------------
// C[M][512] = A[M][Kp] @ B[Kp][512] + bias ; optional keys row-remap.
// CTA tile 128x64, BK=48 (3 ksteps of 16), 256 thr, 8 warps (4m x 2n),
// warp tile 32x32 (2 m-tiles x 4 n-tiles). cp.async double buffered.
#define GN 512
#define TBK 48
// smem: A buf: 128 rows * 112B ; B buf: 48 rows * 144B
#define SA_STRIDE 112
#define SB_STRIDE 144
#define SA_BYTES (128*SA_STRIDE)      // 14336
#define SB_BYTES (TBK*SB_STRIDE)      // 6912
#define SMEM_TOTAL (2*SA_BYTES + 2*SB_BYTES)   // 42496

__global__ __launch_bounds__(256) void gemm_bf16_kernel(
    const __nv_bfloat16* __restrict__ A, int lda,
    const __nv_bfloat16* __restrict__ B,
    const float* __restrict__ bias,
    float* __restrict__ C,
    int M, int Kp, int remapKeys)
{
    __shared__ __align__(16) char smem[SMEM_TOTAL];
    const uint32_t sbase = smem_u32(smem);

    const int tid = threadIdx.x;
    const int lane = tid & 31;
    const int wid = tid >> 5;
    const int warp_m = wid >> 1;       // 0..3
    const int warp_n = wid & 1;        // 0..1

    const int m0 = blockIdx.y * 128;
    const int n0 = blockIdx.x * 64;

    // ldmatrix per-lane base offsets
    const int g = lane >> 3, r8 = lane & 7;
    const uint32_t a_off = (uint32_t)((warp_m * 32 + (g & 1) * 8 + r8) * SA_STRIDE + (g >> 1) * 16);
    const uint32_t b_off = (uint32_t)(((g & 1) * 8 + r8) * SB_STRIDE + (warp_n * 32 + (g >> 1) * 8) * 2);

    float acc[2][4][4];
#pragma unroll
    for (int i = 0; i < 2; i++)
#pragma unroll
        for (int j = 0; j < 4; j++)
#pragma unroll
            for (int k = 0; k < 4; k++) acc[i][j][k] = 0.f;

    const int T = Kp / TBK;

    // ---- tile loader ----
    auto load_tile = [&](int kt, int d) {
        const uint32_t sA = sbase + d * SA_BYTES;
        const uint32_t sB = sbase + 2 * SA_BYTES + d * SB_BYTES;
        // A: 128 rows x 96B = 768 x 16B chunks
#pragma unroll
        for (int i = 0; i < 3; i++) {
            int c = tid + i * 256;
            int row = c / 6, cc = c - row * 6;
            uint32_t dst = sA + (uint32_t)(row * SA_STRIDE + cc * 16);
            const __nv_bfloat16* src = A + (size_t)(m0 + row) * lda + kt * TBK + cc * 8;
            int sz = (m0 + row < M) ? 16 : 0;
            cp_async16(dst, src, sz);
        }
        // B: 48 rows x 128B = 384 x 16B chunks
        for (int c = tid; c < 384; c += 256) {
            int row = c >> 3, cc = c & 7;
            uint32_t dst = sB + (uint32_t)(row * SB_STRIDE + cc * 16);
            const __nv_bfloat16* src = B + (size_t)(kt * TBK + row) * GN + n0 + cc * 8;
            cp_async16(dst, src, 16);
        }
        cp_commit();
    };

    load_tile(0, 0);

    for (int kt = 0; kt < T; kt++) {
        const int d = kt & 1;
        if (kt + 1 < T) {
            load_tile(kt + 1, d ^ 1);
            asm volatile("cp.async.wait_group 1;\n");
        } else {
            asm volatile("cp.async.wait_group 0;\n");
        }
        __syncthreads();

        const uint32_t sA = sbase + d * SA_BYTES;
        const uint32_t sB = sbase + 2 * SA_BYTES + d * SB_BYTES;
#pragma unroll
        for (int ks = 0; ks < 3; ks++) {
            uint32_t a[2][4], b[2][4];
#pragma unroll
            for (int mt = 0; mt < 2; mt++)
                ldsm_x4(a[mt], sA + a_off + (uint32_t)(mt * 16 * SA_STRIDE + ks * 32));
#pragma unroll
            for (int p = 0; p < 2; p++)
                ldsm_x4_t(b[p], sB + b_off + (uint32_t)(p * 32 + ks * 16 * SB_STRIDE));
#pragma unroll
            for (int mt = 0; mt < 2; mt++)
#pragma unroll
                for (int nt = 0; nt < 4; nt++)
                    mma16816(acc[mt][nt], a[mt], &b[nt >> 1][(nt & 1) * 2]);
        }
        __syncthreads();
    }

    // ---- epilogue ----
#pragma unroll
    for (int mt = 0; mt < 2; mt++) {
#pragma unroll
        for (int nt = 0; nt < 4; nt++) {
            int col = n0 + warp_n * 32 + nt * 8 + ((lane & 3) << 1);
            float b0 = bias ? bias[col] : 0.f;
            float b1 = bias ? bias[col + 1] : 0.f;
#pragma unroll
            for (int h = 0; h < 2; h++) {
                int grow = m0 + warp_m * 32 + mt * 16 + (lane >> 2) + h * 8;
                if (grow >= M) continue;
                int orow = grow;
                if (remapKeys) {
                    if (grow < NB * NS) orow = (grow / NS) * NST + grow % NS;
                    else {
                        int rr = grow - NB * NS;
                        orow = (rr / NT) * NST + NS + rr % NT;
                    }
                }
                float2 v;
                v.x = acc[mt][nt][2 * h + 0] + b0;
                v.y = acc[mt][nt][2 * h + 1] + b1;
                *(float2*)&C[(size_t)orow * GN + col] = v;
            }
        }
    }
}

// ---------------- fp32 SIMT GEMM (kept for the tiny ctx GEMM) ---------------
#define BM 128
#define BN 64
#define BK 8
__global__ __launch_bounds__(256) void sgemm_kernel(
    const float* __restrict__ A, const float* __restrict__ B,
    float* __restrict__ C,
    int M, int N, int K, float alpha,
    long long sA, long long sB, long long sC)
{
    A += blockIdx.z * sA;
    B += blockIdx.z * sB;
    C += blockIdx.z * sC;

    __shared__ float As[BK][BM];
    __shared__ float Bs[BK][BN];

    const int tid = threadIdx.x;
    const int bx = blockIdx.x, by = blockIdx.y;

    const int arow = tid >> 1;
    const int acol = (tid & 1) * 4;
    const int brow = tid >> 5;
    const int bcol = (tid & 31) * 2;
    const int tx = tid & 15;
    const int ty = tid >> 4;

    float acc[8][4];
#pragma unroll
    for (int i = 0; i < 8; i++)
#pragma unroll
        for (int j = 0; j < 4; j++) acc[i][j] = 0.f;

    const int gArow = by * BM + arow;
    const float* Arow = (gArow < M) ? A + (long long)gArow * K : nullptr;

    for (int k0 = 0; k0 < K; k0 += BK) {
        float4 av = Arow ? *(const float4*)(Arow + k0 + acol)
                         : make_float4(0.f, 0.f, 0.f, 0.f);
        As[acol + 0][arow] = av.x;
        As[acol + 1][arow] = av.y;
        As[acol + 2][arow] = av.z;
        As[acol + 3][arow] = av.w;
        float2 bv = *(const float2*)(B + (long long)(k0 + brow) * N + bx * BN + bcol);
        Bs[brow][bcol]     = bv.x;
        Bs[brow][bcol + 1] = bv.y;
        __syncthreads();
#pragma unroll
        for (int k = 0; k < BK; k++) {
            float4 a0 = *(const float4*)&As[k][ty * 8];
            float4 a1 = *(const float4*)&As[k][ty * 8 + 4];
            float4 bq = *(const float4*)&Bs[k][tx * 4];
            float ar[8] = {a0.x, a0.y, a0.z, a0.w, a1.x, a1.y, a1.z, a1.w};
            float br[4] = {bq.x, bq.y, bq.z, bq.w};
#pragma unroll
            for (int i = 0; i < 8; i++)
#pragma unroll
                for (int j = 0; j < 4; j++)
                    acc[i][j] = fmaf(ar[i], br[j], acc[i][j]);
        }
        __syncthreads();
    }
#pragma unroll
    for (int i = 0; i < 8; i++) {
        int gr = by * BM + ty * 8 + i;
        if (gr >= M) continue;
#pragma unroll
        for (int j = 0; j < 4; j++) {
            int gc = bx * BN + tx * 4 + j;
            C[(long long)gr * N + gc] = alpha * acc[i][j];
        }
    }
}

// ---------------- scorer ----------------------------------------------------
__global__ __launch_bounds__(256) void scorer_kernel(
    const float* __restrict__ q, const float* __restrict__ stkey,
    float* __restrict__ scores)
{
    __shared__ float qs[16][HD];
    const int b = blockIdx.y;
    const int lt = blockIdx.x;
    const int tid = threadIdx.x;

    const float* qbase = q + ((long long)b * NL + lt * 16) * HD;
    for (int i = tid; i < 16 * HD / 4; i += 256)
        ((float4*)&qs[0][0])[i] = ((const float4*)qbase)[i];
    __syncthreads();

    const int w = tid >> 5, lane = tid & 31;
    for (int r = w; r < NST; r += 8) {
        const float* krow = stkey + ((long long)b * NST + r) * HD;
        float4 kv[4];
#pragma unroll
        for (int i = 0; i < 4; i++)
            kv[i] = *(const float4*)&krow[lane * 4 + i * 128];
#pragma unroll
        for (int l = 0; l < 16; l++) {
            float p = 0.f;
#pragma unroll
            for (int i = 0; i < 4; i++) {
                float4 qv = *(const float4*)&qs[l][lane * 4 + i * 128];
                p = fmaf(kv[i].x, qv.x, p);
                p = fmaf(kv[i].y, qv.y, p);
                p = fmaf(kv[i].z, qv.z, p);
                p = fmaf(kv[i].w, qv.w, p);
            }
#pragma unroll
            for (int o = 16; o; o >>= 1)
                p += __shfl_xor_sync(0xFFFFFFFFu, p, o);
            if (lane == 0)
                scores[((long long)b * NL + lt * 16 + l) * NST + r] = p;
        }
    }
}

// ---------------- factorized softmax ----------------------------------------
__global__ __launch_bounds__(64) void softmax_kernel(
    const float* __restrict__ scores, float* __restrict__ wst)
{
    const int row = blockIdx.x;
    const int tid = threadIdx.x;
    const int lane = tid & 31, w = tid >> 5;
    const float sgn = (w == 0) ? 1.f : -1.f;
    const float invc = 1.f / 32.f;

    const float* sc = scores + (long long)row * NST + w * 100;
    float v[4];
    float mx = -INFINITY;
#pragma unroll
    for (int i = 0; i < 4; i++) {
        int idx = lane + 32 * i;
        float x = (idx < 100) ? sgn * sc[idx] * invc : -INFINITY;
        v[i] = x;
        mx = fmaxf(mx, x);
    }
#pragma unroll
    for (int o = 16; o; o >>= 1)
        mx = fmaxf(mx, __shfl_xor_sync(0xFFFFFFFFu, mx, o));

    float e[4], sum = 0.f;
#pragma unroll
    for (int i = 0; i < 4; i++) {
        int idx = lane + 32 * i;
        e[i] = (idx < 100) ? __expf(v[i] - mx) : 0.f;
        sum += e[i];
    }
#pragma unroll
    for (int o = 16; o; o >>= 1)
        sum += __shfl_xor_sync(0xFFFFFFFFu, sum, o);

    const float inv = sgn / sum;
#pragma unroll
    for (int i = 0; i < 4; i++) {
        int idx = lane + 32 * i;
        if (idx < 100)
            wst[(long long)row * NST + w * 100 + idx] = e[i] * inv;
    }
}

// ---------------- launch -----------------------------------------------------
extern "C" void kernel_launch(void* const* d_in, const int* in_sizes, int n_in,
                              void* d_out, int out_size)
{
    const float* query = (const float*)d_in[0];
    const float* src   = (const float*)d_in[1];
    const float* trg   = (const float*)d_in[2];
    const float* Wq    = (const float*)d_in[3];
    const float* bq    = (const float*)d_in[4];
    const float* Ws    = (const float*)d_in[5];
    const float* bs    = (const float*)d_in[6];
    const float* Wo    = (const float*)d_in[7];
    const float* bo    = (const float*)d_in[8];
    float* out = (float*)d_out;

    __nv_bfloat16 *kA, *Ws2, *oA, *Wq2, *Wo2;
    float *q, *stkey, *scores, *wst, *ctx;
    cudaGetSymbolAddress((void**)&kA,     g_kA);
    cudaGetSymbolAddress((void**)&Ws2,    g_Ws2);
    cudaGetSymbolAddress((void**)&oA,     g_oA);
    cudaGetSymbolAddress((void**)&Wq2,    g_Wq2);
    cudaGetSymbolAddress((void**)&Wo2,    g_Wo2);
    cudaGetSymbolAddress((void**)&q,      g_q);
    cudaGetSymbolAddress((void**)&stkey,  g_stkey);
    cudaGetSymbolAddress((void**)&scores, g_scores);
    cudaGetSymbolAddress((void**)&wst,    g_wst);
    cudaGetSymbolAddress((void**)&ctx,    g_ctx);

    // Conversions (independent -> can all run up front)
    {
        int n;
        n = 800 * FD;     convA_kernel<<<(n + 255) / 256, 256>>>(src, kA, n, FD, KP_KEYS);
        n = 800 * FD;     convA_kernel<<<(n + 255) / 256, 256>>>(trg, kA + (size_t)800 * KP_KEYS, n, FD, KP_KEYS);
        n = FD * HD;      convB_kernel<<<(n + 255) / 256, 256>>>(Ws, Ws2, n, HD);
        n = BLROWS * QD;  convA_kernel<<<(n + 255) / 256, 256>>>(query, oA, n, QD, KP_OUT);
        n = QD * HD;      convB_kernel<<<(n + 255) / 256, 256>>>(Wq, Wq2, n, HD);
        n = (QD + HD) * OD; convB_kernel<<<(n + 255) / 256, 256>>>(Wo, Wo2, n, OD);
    }

    // keys: [1600 x 6144] @ [6144 x 512] + bs -> stkey (remapped per-batch [s;t])
    gemm_bf16_kernel<<<dim3(8, 13), 256>>>(kA, KP_KEYS, Ws2, bs, stkey, 1600, KP_KEYS, 1);

    // q: [1024 x 1536] @ [1536 x 512] + bq
    gemm_bf16_kernel<<<dim3(8, 8), 256>>>(oA, KP_OUT, Wq2, bq, q, BLROWS, KP_Q, 0);

    // scores + factorized softmax
    scorer_kernel<<<dim3(NL / 16, NB), 256>>>(q, stkey, scores);
    softmax_kernel<<<BLROWS, 64>>>(scores, wst);

    // ctx = [ws,-wt] @ st_key / sqrt(2)  (batched fp32 SIMT, small)
    sgemm_kernel<<<dim3(HD / BN, 1, NB), 256>>>(
        wst, stkey, ctx, NL, HD, NST, 0.70710678118654752f,
        (long long)NL * NST, (long long)NST * HD, (long long)NL * HD);

    // ctx -> bf16 pairs into second half of oA
    {
        int n = BLROWS * HD;
        convA_kernel<<<(n + 255) / 256, 256>>>(ctx, oA + KP_Q, n, HD, KP_OUT);
    }

    // out: [1024 x 3072] @ [3072 x 512] + bo
    gemm_bf16_kernel<<<dim3(8, 8), 256>>>(oA, KP_OUT, Wo2, bo, out, BLROWS, KP_OUT, 0);
}